// round 12
// baseline (speedup 1.0000x reference)
#include <cuda_runtime.h>
#include <cuda_bf16.h>
#include <math.h>

// Hybrid: atoms [0, A/2) via scalar Goertzel blocks (fma/MUFU pipes),
//         atoms [A/2, A) via mma.sync GEMM blocks (tensor/LDS pipes).
// Block types interleaved by bid%3 (2 scalar : 1 MMA) so every wave mixes
// pipe usage on each SM. Both paths are the previously-verified R4 / R11
// implementations, rel_err 4.36e-4 each.
#define FR   16
#define NS   32768
#define TPB  256

// ---- scalar path (R4) ----
#define KPT  16
#define SNBX (NS / (TPB * KPT))     // 8 sample-tiles per atom
#define TURN2RAD 1.4629180792671596e-9f   // 2*pi / 2^32

// ---- MMA path (R11) ----
#define PAD  136                    // bf16 per smem row (128+8); 68 words = 4 mod 32
#define SM_PAR 0                    // float4[16]  (also scalar s_c1)
#define SM_C2  256                  // float4[16]  (scalar s_c2)
#define SM_A   512                  // bf16[128*136] = 34816  {Ah | Al}
#define SM_CC  35328                // bf16[ 64*136] = 17408  {Ch | Cl}
#define SM_TOTAL 52736

typedef unsigned u32;

static __device__ __forceinline__ void mma16816(float* d, const u32* a, u32 b0, u32 b1) {
    asm volatile(
        "mma.sync.aligned.m16n8k16.row.col.f32.bf16.bf16.f32 "
        "{%0,%1,%2,%3}, {%4,%5,%6,%7}, {%8,%9}, {%0,%1,%2,%3};"
        : "+f"(d[0]), "+f"(d[1]), "+f"(d[2]), "+f"(d[3])
        : "r"(a[0]), "r"(a[1]), "r"(a[2]), "r"(a[3]), "r"(b0), "r"(b1));
}
static __device__ __forceinline__ void split_bf16(float v, __nv_bfloat16& h, __nv_bfloat16& l) {
    h = __float2bfloat16(v);
    l = __float2bfloat16(v - __bfloat162float(h));
}

// ---------------------------------------------------------------------------
__global__ void __launch_bounds__(TPB, 3)
synth_hybrid_kernel(const float* __restrict__ osc,
                    const float* __restrict__ amp,
                    const float* __restrict__ decay,
                    float* __restrict__ out, int A)
{
    extern __shared__ char smem[];
    const int tid = threadIdx.x;
    const int bid = blockIdx.x;
    const int m3  = bid % 3;

    if (m3 < 2) {
        // =================== scalar Goertzel path (R4) =====================
        const int s    = (bid / 3) * 2 + m3;          // [0, 4A) -> but only 4*(A/2)
        const int a    = s >> 3;                      // atom in [0, A/2)
        const int bx   = s & 7;
        const int base = bx * (TPB * KPT);
        const int J    = bx * KPT;

        float4* s_c1 = (float4*)(smem + SM_PAR);
        float4* s_c2 = (float4*)(smem + SM_C2);

        if (tid < FR) {
            int i = a * FR + tid;
            float o   = osc[i];
            float sgf = (float)(1.0 / (1.0 + exp(-(double)o)));
            float t1  = sgf * sgf;
            float fq  = t1 * 3.14159274101257324219f;
            double f2p = (double)fq * (1.0 / (2.0 * M_PI));
            unsigned phi = (unsigned)llrint(f2p * 4294967296.0);
            unsigned dp  = phi << 8;

            float am = amp[i];
            float a2 = am * am * 0.0625f;

            float dv  = decay[i];
            float sgd = (float)(1.0 / (1.0 + exp(-(double)dv)));
            float d   = 0.7f + sgd * 0.299999f;

            float del = (float)(int)dp * TURN2RAD;
            float rc  = 2.0f * d * __cosf(del);
            float nc2 = -(d * d);

            float l2d = (float)log2((double)d);
            float Eh0 = a2 * exp2f((float)J * l2d);
            float Eh1 = Eh0 * d;

            s_c1[tid] = make_float4(__uint_as_float(phi), __uint_as_float(dp), rc, nc2);
            s_c2[tid] = make_float4(Eh0, Eh1, a2 * d, d - 1.0f);
        }
        __syncthreads();

        const int  h  = tid >> 7;
        const float w = fmaf((float)tid, 0.00390625f,
                             h ? -0.498046875f : 0.501953125f);
        const unsigned tk1 = (unsigned)(base + tid + 1);
        const bool fix_first = (bx == 0)        && (h == 0);
        const bool fix_last  = (bx == SNBX - 1) && (h == 1);

        float acc[KPT];
#pragma unroll
        for (int k = 0; k < KPT; k++) acc[k] = 0.0f;

#pragma unroll 4
        for (int f = 0; f < FR; f++) {
            const float4 c1 = s_c1[f];
            const float4 c2 = s_c2[f];
            const unsigned phi = __float_as_uint(c1.x);
            const unsigned dp  = __float_as_uint(c1.y);
            const float rc  = c1.z, nc2 = c1.w;
            const float Eh  = h ? c2.y : c2.x;
            const float dm1 = c2.w;
            const float wf  = fmaf(w, dm1, 1.0f);
            const float Ew  = Eh * wf;

            unsigned p0 = tk1 * phi;
            unsigned p1 = p0 + dp;
            float s0 = __sinf((float)(int)p0 * TURN2RAD);
            float s1 = __sinf((float)(int)p1 * TURN2RAD);

            float ykm2 = s0 * Ew;
            float ykm1 = s1 * fmaf(Ew, dm1, Ew);

            acc[0] = fmaf(s0, fix_first ? c2.z : Ew, acc[0]);
            acc[1] += ykm1;

#pragma unroll
            for (int k = 2; k < KPT; k++) {
                float y = fmaf(rc, ykm1, nc2 * ykm2);
                if (k == KPT - 1 && fix_last)
                    acc[k] += __fdividef(y, wf);
                else
                    acc[k] += y;
                ykm2 = ykm1;  ykm1 = y;
            }
        }

        float* o = out + (size_t)a * NS + base + tid;
#pragma unroll
        for (int k = 0; k < KPT; k++)
            o[k * TPB] = acc[k];

    } else {
        // ======================= MMA GEMM path (R11) =======================
        const int m  = bid / 3;                        // [0, 2*(A/2))
        const int a  = (A >> 1) + (m >> 2);            // atom in [A/2, A)
        const int nh = m & 3;                          // T-quarter

        float4*        par = (float4*)(smem + SM_PAR);
        __nv_bfloat16* As  = (__nv_bfloat16*)(smem + SM_A);
        __nv_bfloat16* Cs  = (__nv_bfloat16*)(smem + SM_CC);

        if (tid < FR) {
            int i = a * FR + tid;
            float o   = osc[i];
            float sgf = (float)(1.0 / (1.0 + exp(-(double)o)));
            float fq  = (sgf * sgf) * 3.14159274101257324219f;
            double f2p = (double)fq * (1.0 / (2.0 * M_PI));
            u32 phi = (u32)llrint(f2p * 4294967296.0);

            float am = amp[i];
            float P  = am * am * 0.0625f;

            float dv  = decay[i];
            float sgd = (float)(1.0 / (1.0 + exp(-(double)dv)));
            float d   = 0.7f + sgd * 0.299999f;
            float l2d = (float)log2((double)d);
            par[tid] = make_float4(__uint_as_float(phi), P, d, l2d);
        }
        __syncthreads();

        for (int idx = tid; idx < FR * 128; idx += TPB) {
            int tau = idx & 127, f = idx >> 7;
            u32 phi = __float_as_uint(par[f].x);
            u32 p   = (u32)tau * phi;
            float x = (float)(int)p * TURN2RAD;
            float sv = __sinf(x), cv = __cosf(x);
            float ts = (float)tau * 0.0078125f;
            float v[4] = { sv, cv, sv * ts, cv * ts };
            __nv_bfloat16 hh[4], ll[4];
#pragma unroll
            for (int q = 0; q < 4; q++) split_bf16(v[q], hh[q], ll[q]);
            __nv_bfloat16* row = As + tau * PAD + 4 * f;
            *(__nv_bfloat162*)(row)      = __nv_bfloat162(hh[0], hh[1]);
            *(__nv_bfloat162*)(row + 2)  = __nv_bfloat162(hh[2], hh[3]);
            *(__nv_bfloat162*)(row + 64) = __nv_bfloat162(ll[0], ll[1]);
            *(__nv_bfloat162*)(row + 66) = __nv_bfloat162(ll[2], ll[3]);
        }

        for (int idx = tid; idx < FR * 64; idx += TPB) {
            int Tl = idx & 63, f = idx >> 6;
            int T  = nh * 64 + Tl;
            float4 pr = par[f];
            u32 phi = __float_as_uint(pr.x);
            float P = pr.y, d = pr.z, l2d = pr.w;

            float al, be;
            if (T == 0)        { al = exp2f(l2d);          be = 0.0f; }
            else if (T == 255) { al = exp2f(128.0f * l2d); be = 0.0f; }
            else {
                int   i0 = (T - 1) >> 1;
                float w0 = (T & 1) ? 0.001953125f : 0.501953125f;
                float dj = exp2f((float)(i0 + 1) * l2d);
                float dm1 = d - 1.0f;
                al = dj * fmaf(w0, dm1, 1.0f);
                be = dj * dm1 * 0.5f;
            }
            u32 p   = (u32)(128 * T + 1) * phi;
            float x = (float)(int)p * TURN2RAD;
            float SA = __sinf(x), CA = __cosf(x);
            float Pal = P * al, Pbe = P * be;
            float e[4] = { Pal * CA, Pal * SA, Pbe * CA, Pbe * SA };
            __nv_bfloat16 hh[4], ll[4];
#pragma unroll
            for (int q = 0; q < 4; q++) split_bf16(e[q], hh[q], ll[q]);
            __nv_bfloat16* row = Cs + Tl * PAD + 4 * f;
            *(__nv_bfloat162*)(row)      = __nv_bfloat162(hh[0], hh[1]);
            *(__nv_bfloat162*)(row + 2)  = __nv_bfloat162(hh[2], hh[3]);
            *(__nv_bfloat162*)(row + 64) = __nv_bfloat162(ll[0], ll[1]);
            *(__nv_bfloat162*)(row + 66) = __nv_bfloat162(ll[2], ll[3]);
        }
        __syncthreads();

        const int w    = tid >> 5, lane = tid & 31;
        const int g    = lane >> 2, qi = lane & 3;
        const int mh   = w >> 2,    nw = w & 3;

        float acc[4][2][4];
#pragma unroll
        for (int mt = 0; mt < 4; mt++)
#pragma unroll
            for (int nt = 0; nt < 2; nt++)
#pragma unroll
                for (int q = 0; q < 4; q++) acc[mt][nt][q] = 0.0f;

#pragma unroll 1
        for (int kq = 0; kq < 4; kq++) {
            const int ka = kq * 16;
            u32 bH[2][2], bL[2][2];
#pragma unroll
            for (int nt = 0; nt < 2; nt++) {
                const __nv_bfloat16* rc = Cs + (nw * 16 + nt * 8 + g) * PAD + ka + 2 * qi;
                bH[nt][0] = *(const u32*)(rc);
                bH[nt][1] = *(const u32*)(rc + 8);
                bL[nt][0] = *(const u32*)(rc + 64);
                bL[nt][1] = *(const u32*)(rc + 72);
            }
            u32 afr[4][4];
#pragma unroll
            for (int mt = 0; mt < 4; mt++) {
                const __nv_bfloat16* r0 = As + (mh * 64 + mt * 16 + g) * PAD + ka + 2 * qi;
                afr[mt][0] = *(const u32*)(r0);
                afr[mt][1] = *(const u32*)(r0 + 8 * PAD);
                afr[mt][2] = *(const u32*)(r0 + 8);
                afr[mt][3] = *(const u32*)(r0 + 8 * PAD + 8);
            }
#pragma unroll
            for (int nt = 0; nt < 2; nt++)
#pragma unroll
                for (int mt = 0; mt < 4; mt++)
                    mma16816(acc[mt][nt], afr[mt], bH[nt][0], bH[nt][1]);
#pragma unroll
            for (int nt = 0; nt < 2; nt++)
#pragma unroll
                for (int mt = 0; mt < 4; mt++)
                    mma16816(acc[mt][nt], afr[mt], bL[nt][0], bL[nt][1]);
#pragma unroll
            for (int mt = 0; mt < 4; mt++) {
                const __nv_bfloat16* r0 = As + (mh * 64 + mt * 16 + g) * PAD + 64 + ka + 2 * qi;
                afr[mt][0] = *(const u32*)(r0);
                afr[mt][1] = *(const u32*)(r0 + 8 * PAD);
                afr[mt][2] = *(const u32*)(r0 + 8);
                afr[mt][3] = *(const u32*)(r0 + 8 * PAD + 8);
            }
#pragma unroll
            for (int nt = 0; nt < 2; nt++)
#pragma unroll
                for (int mt = 0; mt < 4; mt++)
                    mma16816(acc[mt][nt], afr[mt], bH[nt][0], bH[nt][1]);
        }

        float* ob = out + (size_t)a * NS + (size_t)(nh * 64 + nw * 16) * 128;
#pragma unroll
        for (int nt = 0; nt < 2; nt++)
#pragma unroll
            for (int mt = 0; mt < 4; mt++) {
                float* b = ob + (size_t)(nt * 8 + 2 * qi) * 128 + mh * 64 + mt * 16 + g;
                b[0]   = acc[mt][nt][0];
                b[128] = acc[mt][nt][1];
                b[8]   = acc[mt][nt][2];
                b[136] = acc[mt][nt][3];
            }
    }
}

// ---------------------------------------------------------------------------
extern "C" void kernel_launch(void* const* d_in, const int* in_sizes, int n_in,
                              void* d_out, int out_size)
{
    const float* osc   = (const float*)d_in[0];
    const float* amp   = (const float*)d_in[1];
    const float* decay = (const float*)d_in[2];

    int A = in_sizes[0] / FR;     // 128
    // scalar blocks: 8 per atom * A/2 atoms = 4A; MMA blocks: 4 per atom * A/2 = 2A.
    // Interleaved 2:1 by bid%3 -> total 6A blocks.
    int nblocks = 6 * A;

    cudaFuncSetAttribute(synth_hybrid_kernel,
                         cudaFuncAttributeMaxDynamicSharedMemorySize, SM_TOTAL);
    synth_hybrid_kernel<<<nblocks, TPB, SM_TOTAL>>>(osc, amp, decay, (float*)d_out, A);
}

// round 13
// speedup vs baseline: 1.1971x; 1.1971x over previous
#include <cuda_runtime.h>
#include <cuda_bf16.h>
#include <math.h>

// Fixed shape: A=128 atoms, FR=16 partials, NS=32768 samples, NF=128 frames.
// t = 128*T + tau, T in [0,256), tau in [0,128).
// out[a, 128T+tau] = Ah*Ch + Al*Ch + Ah*Cl (hi/lo bf16 split; K-blocks of 64
// via address mapping). CTA = (atom, T-quarter): grid (128, 4) = 512 CTAs.
// Register-lean mt-pair MMA structure -> 64 regs -> 4 CTAs/SM -> ONE wave.
#define FR   16
#define NS   32768
#define TPB  256
#define PAD  136                    // bf16 per smem row (128+8); 68 words = 4 mod 32

#define TURN2RAD 1.4629180792671596e-9f   // 2*pi / 2^32

// smem layout (bytes)
#define SM_PAR 0                    // float4[16]
#define SM_A   256                  // bf16[128*136] = 34816  {Ah | Al}
#define SM_C   35072                // bf16[ 64*136] = 17408  {Ch | Cl}
#define SM_TOTAL 52480

typedef unsigned u32;

static __device__ __forceinline__ void mma16816(float* d, const u32* a, u32 b0, u32 b1) {
    asm volatile(
        "mma.sync.aligned.m16n8k16.row.col.f32.bf16.bf16.f32 "
        "{%0,%1,%2,%3}, {%4,%5,%6,%7}, {%8,%9}, {%0,%1,%2,%3};"
        : "+f"(d[0]), "+f"(d[1]), "+f"(d[2]), "+f"(d[3])
        : "r"(a[0]), "r"(a[1]), "r"(a[2]), "r"(a[3]), "r"(b0), "r"(b1));
}

static __device__ __forceinline__ void split_bf16(float v, __nv_bfloat16& h, __nv_bfloat16& l) {
    h = __float2bfloat16(v);
    l = __float2bfloat16(v - __bfloat162float(h));
}

// ---------------------------------------------------------------------------
__global__ void __launch_bounds__(TPB, 4)
synth_mma_kernel(const float* __restrict__ osc,
                 const float* __restrict__ amp,
                 const float* __restrict__ decay,
                 float* __restrict__ out)
{
    extern __shared__ char smem[];
    float4*        par = (float4*)(smem + SM_PAR);    // {phi bits, P, d, log2 d}
    __nv_bfloat16* As  = (__nv_bfloat16*)(smem + SM_A);
    __nv_bfloat16* Cs  = (__nv_bfloat16*)(smem + SM_C);

    const int tid = threadIdx.x;
    const int a   = blockIdx.x;
    const int nh  = blockIdx.y;                       // T-quarter: T = nh*64 + Tl

    // --- per-partial params (replicate reference fp32 rounding chain) ---
    if (tid < FR) {
        int i = a * FR + tid;
        float o   = osc[i];
        float sgf = (float)(1.0 / (1.0 + exp(-(double)o)));
        float fq  = (sgf * sgf) * 3.14159274101257324219f;     // fl32(pi)
        double f2p = (double)fq * (1.0 / (2.0 * M_PI));
        u32 phi = (u32)llrint(f2p * 4294967296.0);             // Q0.32 turns/sample

        float am = amp[i];
        float P  = am * am * 0.0625f;

        float dv  = decay[i];
        float sgd = (float)(1.0 / (1.0 + exp(-(double)dv)));
        float d   = 0.7f + sgd * 0.299999f;
        float l2d = (float)log2((double)d);
        par[tid] = make_float4(__uint_as_float(phi), P, d, l2d);
    }
    __syncthreads();

    // --- A (basis) tile {Ah | Al}: 128 tau rows ---
    for (int idx = tid; idx < FR * 128; idx += TPB) {
        int tau = idx & 127, f = idx >> 7;
        u32 phi = __float_as_uint(par[f].x);
        u32 p   = (u32)tau * phi;
        float x = (float)(int)p * TURN2RAD;
        float s = __sinf(x), c = __cosf(x);
        float ts = (float)tau * 0.0078125f;
        float v[4] = { s, c, s * ts, c * ts };
        __nv_bfloat16 h[4], l[4];
#pragma unroll
        for (int q = 0; q < 4; q++) split_bf16(v[q], h[q], l[q]);
        __nv_bfloat16* row = As + tau * PAD + 4 * f;
        *(__nv_bfloat162*)(row)      = __nv_bfloat162(h[0], h[1]);   // Ah
        *(__nv_bfloat162*)(row + 2)  = __nv_bfloat162(h[2], h[3]);
        *(__nv_bfloat162*)(row + 64) = __nv_bfloat162(l[0], l[1]);   // Al
        *(__nv_bfloat162*)(row + 66) = __nv_bfloat162(l[2], l[3]);
    }

    // --- C (coefficient) tile {Ch | Cl}: 64 local T rows ---
    for (int idx = tid; idx < FR * 64; idx += TPB) {
        int Tl = idx & 63, f = idx >> 6;
        int T  = nh * 64 + Tl;
        float4 pr = par[f];
        u32 phi = __float_as_uint(pr.x);
        float P = pr.y, d = pr.z, l2d = pr.w;

        float al, be;
        if (T == 0)        { al = exp2f(l2d);          be = 0.0f; }
        else if (T == 255) { al = exp2f(128.0f * l2d); be = 0.0f; }
        else {
            int   i0 = (T - 1) >> 1;
            float w0 = (T & 1) ? 0.001953125f : 0.501953125f;
            float dj = exp2f((float)(i0 + 1) * l2d);   // d^(i0+1)
            float dm1 = d - 1.0f;
            al = dj * fmaf(w0, dm1, 1.0f);
            be = dj * dm1 * 0.5f;              // coefficient of ts = tau/128
        }
        u32 p   = (u32)(128 * T + 1) * phi;
        float x = (float)(int)p * TURN2RAD;
        float SA = __sinf(x), CA = __cosf(x);
        float Pal = P * al, Pbe = P * be;
        float e[4] = { Pal * CA, Pal * SA, Pbe * CA, Pbe * SA };
        __nv_bfloat16 h[4], l[4];
#pragma unroll
        for (int q = 0; q < 4; q++) split_bf16(e[q], h[q], l[q]);
        __nv_bfloat16* row = Cs + Tl * PAD + 4 * f;
        *(__nv_bfloat162*)(row)      = __nv_bfloat162(h[0], h[1]);   // Ch
        *(__nv_bfloat162*)(row + 2)  = __nv_bfloat162(h[2], h[3]);
        *(__nv_bfloat162*)(row + 64) = __nv_bfloat162(l[0], l[1]);   // Cl
        *(__nv_bfloat162*)(row + 66) = __nv_bfloat162(l[2], l[3]);
    }
    __syncthreads();

    // --- MMA: D[128 tau x 64 Tl]. warp = (mh tau-half, nw 16-T stripe). ---
    const int w    = tid >> 5, lane = tid & 31;
    const int g    = lane >> 2, qi = lane & 3;
    const int mh   = w >> 2,    nw = w & 3;

    float acc[4][2][4];
#pragma unroll
    for (int mt = 0; mt < 4; mt++)
#pragma unroll
        for (int nt = 0; nt < 2; nt++)
#pragma unroll
            for (int q = 0; q < 4; q++) acc[mt][nt][q] = 0.0f;

    // kq loop; A-fragments processed in mt-PAIRS to keep live regs <= 64.
#pragma unroll 1
    for (int kq = 0; kq < 4; kq++) {
        const int ka = kq * 16;
        u32 bH[2][2], bL[2][2];
#pragma unroll
        for (int nt = 0; nt < 2; nt++) {
            const __nv_bfloat16* rc = Cs + (nw * 16 + nt * 8 + g) * PAD + ka + 2 * qi;
            bH[nt][0] = *(const u32*)(rc);
            bH[nt][1] = *(const u32*)(rc + 8);
            bL[nt][0] = *(const u32*)(rc + 64);
            bL[nt][1] = *(const u32*)(rc + 72);
        }
#pragma unroll
        for (int p2 = 0; p2 < 2; p2++) {             // mt pair {2*p2, 2*p2+1}
            u32 af[2][4];
#pragma unroll
            for (int m2 = 0; m2 < 2; m2++) {         // Ah fragments
                const int mt = 2 * p2 + m2;
                const __nv_bfloat16* r0 = As + (mh * 64 + mt * 16 + g) * PAD + ka + 2 * qi;
                af[m2][0] = *(const u32*)(r0);
                af[m2][1] = *(const u32*)(r0 + 8 * PAD);
                af[m2][2] = *(const u32*)(r0 + 8);
                af[m2][3] = *(const u32*)(r0 + 8 * PAD + 8);
            }
#pragma unroll
            for (int nt = 0; nt < 2; nt++)
#pragma unroll
                for (int m2 = 0; m2 < 2; m2++)
                    mma16816(acc[2 * p2 + m2][nt], af[m2], bH[nt][0], bH[nt][1]); // Ah*Ch
#pragma unroll
            for (int nt = 0; nt < 2; nt++)
#pragma unroll
                for (int m2 = 0; m2 < 2; m2++)
                    mma16816(acc[2 * p2 + m2][nt], af[m2], bL[nt][0], bL[nt][1]); // Ah*Cl
#pragma unroll
            for (int m2 = 0; m2 < 2; m2++) {         // Al fragments (reuse regs)
                const int mt = 2 * p2 + m2;
                const __nv_bfloat16* r0 = As + (mh * 64 + mt * 16 + g) * PAD + 64 + ka + 2 * qi;
                af[m2][0] = *(const u32*)(r0);
                af[m2][1] = *(const u32*)(r0 + 8 * PAD);
                af[m2][2] = *(const u32*)(r0 + 8);
                af[m2][3] = *(const u32*)(r0 + 8 * PAD + 8);
            }
#pragma unroll
            for (int nt = 0; nt < 2; nt++)
#pragma unroll
                for (int m2 = 0; m2 < 2; m2++)
                    mma16816(acc[2 * p2 + m2][nt], af[m2], bH[nt][0], bH[nt][1]); // Al*Ch
        }
    }

    // --- epilogue: direct STG.32; each quad-row hits one exact 32B sector ---
    float* ob = out + (size_t)a * NS + (size_t)(nh * 64 + nw * 16) * 128;
#pragma unroll
    for (int nt = 0; nt < 2; nt++)
#pragma unroll
        for (int mt = 0; mt < 4; mt++) {
            float* b = ob + (size_t)(nt * 8 + 2 * qi) * 128 + mh * 64 + mt * 16 + g;
            b[0]   = acc[mt][nt][0];
            b[128] = acc[mt][nt][1];
            b[8]   = acc[mt][nt][2];
            b[136] = acc[mt][nt][3];
        }
}

// ---------------------------------------------------------------------------
extern "C" void kernel_launch(void* const* d_in, const int* in_sizes, int n_in,
                              void* d_out, int out_size)
{
    const float* osc   = (const float*)d_in[0];
    const float* amp   = (const float*)d_in[1];
    const float* decay = (const float*)d_in[2];

    int A = in_sizes[0] / FR;

    cudaFuncSetAttribute(synth_mma_kernel,
                         cudaFuncAttributeMaxDynamicSharedMemorySize, SM_TOTAL);
    dim3 grid(A, 4);
    synth_mma_kernel<<<grid, TPB, SM_TOTAL>>>(osc, amp, decay, (float*)d_out);
}

// round 14
// speedup vs baseline: 1.2851x; 1.0735x over previous
#include <cuda_runtime.h>
#include <cuda_bf16.h>
#include <math.h>

// Fixed shape: A=128 atoms, FR=16 partials, NS=32768 samples, NF=128 frames.
// t = 128*T + tau, T in [0,256), tau in [0,128).
// out[a, 128T+tau] = Ah*Ch + Al*Ch + Ah*Cl (hi/lo bf16 split; K-blocks of 64
// via address mapping). CTA = (atom, T-quarter): grid (128, 4) = 512 CTAs,
// one co-resident wave at 4 CTAs/SM. Fragment loads via ldmatrix.x4.
#define FR   16
#define NS   32768
#define TPB  256
#define PAD  136                    // bf16 per smem row (128+8); 68 words = 4 mod 32

#define TURN2RAD 1.4629180792671596e-9f   // 2*pi / 2^32

// smem layout (bytes)
#define SM_PAR 0                    // float4[16]
#define SM_A   256                  // bf16[128*136] = 34816  {Ah | Al}
#define SM_C   35072                // bf16[ 64*136] = 17408  {Ch | Cl}
#define SM_TOTAL 52480

typedef unsigned u32;

static __device__ __forceinline__ void mma16816(float* d, const u32* a, u32 b0, u32 b1) {
    asm volatile(
        "mma.sync.aligned.m16n8k16.row.col.f32.bf16.bf16.f32 "
        "{%0,%1,%2,%3}, {%4,%5,%6,%7}, {%8,%9}, {%0,%1,%2,%3};"
        : "+f"(d[0]), "+f"(d[1]), "+f"(d[2]), "+f"(d[3])
        : "r"(a[0]), "r"(a[1]), "r"(a[2]), "r"(a[3]), "r"(b0), "r"(b1));
}

static __device__ __forceinline__ void ldsm4(u32& r0, u32& r1, u32& r2, u32& r3, u32 addr) {
    asm volatile("ldmatrix.sync.aligned.m8n8.x4.shared.b16 {%0,%1,%2,%3}, [%4];"
                 : "=r"(r0), "=r"(r1), "=r"(r2), "=r"(r3) : "r"(addr));
}

static __device__ __forceinline__ void split_bf16(float v, __nv_bfloat16& h, __nv_bfloat16& l) {
    h = __float2bfloat16(v);
    l = __float2bfloat16(v - __bfloat162float(h));
}

// ---------------------------------------------------------------------------
__global__ void __launch_bounds__(TPB, 4)
synth_mma_kernel(const float* __restrict__ osc,
                 const float* __restrict__ amp,
                 const float* __restrict__ decay,
                 float* __restrict__ out)
{
    extern __shared__ char smem[];
    float4*        par = (float4*)(smem + SM_PAR);    // {phi bits, P, d, log2 d}
    __nv_bfloat16* As  = (__nv_bfloat16*)(smem + SM_A);
    __nv_bfloat16* Cs  = (__nv_bfloat16*)(smem + SM_C);

    const int tid = threadIdx.x;
    const int a   = blockIdx.x;
    const int nh  = blockIdx.y;                       // T-quarter: T = nh*64 + Tl

    // --- per-partial params (replicate reference fp32 rounding chain) ---
    if (tid < FR) {
        int i = a * FR + tid;
        float o   = osc[i];
        float sgf = (float)(1.0 / (1.0 + exp(-(double)o)));
        float fq  = (sgf * sgf) * 3.14159274101257324219f;     // fl32(pi)
        double f2p = (double)fq * (1.0 / (2.0 * M_PI));
        u32 phi = (u32)llrint(f2p * 4294967296.0);             // Q0.32 turns/sample

        float am = amp[i];
        float P  = am * am * 0.0625f;

        float dv  = decay[i];
        float sgd = (float)(1.0 / (1.0 + exp(-(double)dv)));
        float d   = 0.7f + sgd * 0.299999f;
        float l2d = (float)log2((double)d);
        par[tid] = make_float4(__uint_as_float(phi), P, d, l2d);
    }
    __syncthreads();

    // --- A (basis) tile {Ah | Al}: 128 tau rows ---
    for (int idx = tid; idx < FR * 128; idx += TPB) {
        int tau = idx & 127, f = idx >> 7;
        u32 phi = __float_as_uint(par[f].x);
        u32 p   = (u32)tau * phi;
        float x = (float)(int)p * TURN2RAD;
        float s = __sinf(x), c = __cosf(x);
        float ts = (float)tau * 0.0078125f;
        float v[4] = { s, c, s * ts, c * ts };
        __nv_bfloat16 h[4], l[4];
#pragma unroll
        for (int q = 0; q < 4; q++) split_bf16(v[q], h[q], l[q]);
        __nv_bfloat16* row = As + tau * PAD + 4 * f;
        *(__nv_bfloat162*)(row)      = __nv_bfloat162(h[0], h[1]);   // Ah
        *(__nv_bfloat162*)(row + 2)  = __nv_bfloat162(h[2], h[3]);
        *(__nv_bfloat162*)(row + 64) = __nv_bfloat162(l[0], l[1]);   // Al
        *(__nv_bfloat162*)(row + 66) = __nv_bfloat162(l[2], l[3]);
    }

    // --- C (coefficient) tile {Ch | Cl}: 64 local T rows ---
    for (int idx = tid; idx < FR * 64; idx += TPB) {
        int Tl = idx & 63, f = idx >> 6;
        int T  = nh * 64 + Tl;
        float4 pr = par[f];
        u32 phi = __float_as_uint(pr.x);
        float P = pr.y, d = pr.z, l2d = pr.w;

        float al, be;
        if (T == 0)        { al = exp2f(l2d);          be = 0.0f; }
        else if (T == 255) { al = exp2f(128.0f * l2d); be = 0.0f; }
        else {
            int   i0 = (T - 1) >> 1;
            float w0 = (T & 1) ? 0.001953125f : 0.501953125f;
            float dj = exp2f((float)(i0 + 1) * l2d);   // d^(i0+1)
            float dm1 = d - 1.0f;
            al = dj * fmaf(w0, dm1, 1.0f);
            be = dj * dm1 * 0.5f;              // coefficient of ts = tau/128
        }
        u32 p   = (u32)(128 * T + 1) * phi;
        float x = (float)(int)p * TURN2RAD;
        float SA = __sinf(x), CA = __cosf(x);
        float Pal = P * al, Pbe = P * be;
        float e[4] = { Pal * CA, Pal * SA, Pbe * CA, Pbe * SA };
        __nv_bfloat16 h[4], l[4];
#pragma unroll
        for (int q = 0; q < 4; q++) split_bf16(e[q], h[q], l[q]);
        __nv_bfloat16* row = Cs + Tl * PAD + 4 * f;
        *(__nv_bfloat162*)(row)      = __nv_bfloat162(h[0], h[1]);   // Ch
        *(__nv_bfloat162*)(row + 2)  = __nv_bfloat162(h[2], h[3]);
        *(__nv_bfloat162*)(row + 64) = __nv_bfloat162(l[0], l[1]);   // Cl
        *(__nv_bfloat162*)(row + 66) = __nv_bfloat162(l[2], l[3]);
    }
    __syncthreads();

    // --- MMA: D[128 tau x 64 Tl]. warp = (mh tau-half, nw 16-T stripe). ---
    const int w    = tid >> 5, lane = tid & 31;
    const int mh   = w >> 2,   nw   = w & 3;
    const int g    = lane >> 2, qi  = lane & 3;

    // ldmatrix per-lane source addresses (byte, shared window):
    //  A mats (per 16x16 fragment): sel = lane>>3: {r+0,c+0},{r+8,c+0},{r+0,c+8},{r+8,c+8}
    const int arof = (lane & 7) + ((lane >> 3) & 1) * 8;
    const int acof = (lane >> 4) * 8;
    //  B quad: {Ch k+0}, {Ch k+8}, {Cl k+64}, {Cl k+72}
    const int brof = lane & 7;
    const int bcof = ((lane >> 3) & 1) * 8 + (lane >> 4) * 64;

    const u32 sbA = (u32)__cvta_generic_to_shared(As);
    const u32 sbC = (u32)__cvta_generic_to_shared(Cs);
    u32 apt[4], bpt[2];
#pragma unroll
    for (int mt = 0; mt < 4; mt++)
        apt[mt] = sbA + (u32)(((mh * 64 + mt * 16 + arof) * PAD + acof) * 2);
#pragma unroll
    for (int nt = 0; nt < 2; nt++)
        bpt[nt] = sbC + (u32)(((nw * 16 + nt * 8 + brof) * PAD + bcof) * 2);

    float acc[4][2][4];
#pragma unroll
    for (int mt = 0; mt < 4; mt++)
#pragma unroll
        for (int nt = 0; nt < 2; nt++)
#pragma unroll
            for (int q = 0; q < 4; q++) acc[mt][nt][q] = 0.0f;

#pragma unroll 1
    for (int kq = 0; kq < 4; kq++) {
        const u32 kb = (u32)kq * 32;                  // 16 bf16 per K-step
        u32 bH[2][2], bL[2][2];
#pragma unroll
        for (int nt = 0; nt < 2; nt++)
            ldsm4(bH[nt][0], bH[nt][1], bL[nt][0], bL[nt][1], bpt[nt] + kb);

#pragma unroll
        for (int p2 = 0; p2 < 2; p2++) {              // mt pair {2p2, 2p2+1}
            u32 af[2][4];
#pragma unroll
            for (int m2 = 0; m2 < 2; m2++)            // Ah fragments
                ldsm4(af[m2][0], af[m2][1], af[m2][2], af[m2][3],
                      apt[2 * p2 + m2] + kb);
#pragma unroll
            for (int nt = 0; nt < 2; nt++)
#pragma unroll
                for (int m2 = 0; m2 < 2; m2++)
                    mma16816(acc[2 * p2 + m2][nt], af[m2], bH[nt][0], bH[nt][1]); // Ah*Ch
#pragma unroll
            for (int nt = 0; nt < 2; nt++)
#pragma unroll
                for (int m2 = 0; m2 < 2; m2++)
                    mma16816(acc[2 * p2 + m2][nt], af[m2], bL[nt][0], bL[nt][1]); // Ah*Cl
#pragma unroll
            for (int m2 = 0; m2 < 2; m2++)            // Al fragments (reuse regs)
                ldsm4(af[m2][0], af[m2][1], af[m2][2], af[m2][3],
                      apt[2 * p2 + m2] + kb + 128);   // +64 bf16
#pragma unroll
            for (int nt = 0; nt < 2; nt++)
#pragma unroll
                for (int m2 = 0; m2 < 2; m2++)
                    mma16816(acc[2 * p2 + m2][nt], af[m2], bH[nt][0], bH[nt][1]); // Al*Ch
        }
    }

    // --- epilogue: direct STG.32; each quad-row hits one exact 32B sector ---
    float* ob = out + (size_t)a * NS + (size_t)(nh * 64 + nw * 16) * 128;
#pragma unroll
    for (int nt = 0; nt < 2; nt++)
#pragma unroll
        for (int mt = 0; mt < 4; mt++) {
            float* b = ob + (size_t)(nt * 8 + 2 * qi) * 128 + mh * 64 + mt * 16 + g;
            b[0]   = acc[mt][nt][0];
            b[128] = acc[mt][nt][1];
            b[8]   = acc[mt][nt][2];
            b[136] = acc[mt][nt][3];
        }
}

// ---------------------------------------------------------------------------
extern "C" void kernel_launch(void* const* d_in, const int* in_sizes, int n_in,
                              void* d_out, int out_size)
{
    const float* osc   = (const float*)d_in[0];
    const float* amp   = (const float*)d_in[1];
    const float* decay = (const float*)d_in[2];

    int A = in_sizes[0] / FR;

    cudaFuncSetAttribute(synth_mma_kernel,
                         cudaFuncAttributeMaxDynamicSharedMemorySize, SM_TOTAL);
    dim3 grid(A, 4);
    synth_mma_kernel<<<grid, TPB, SM_TOTAL>>>(osc, amp, decay, (float*)d_out);
}